// round 1
// baseline (speedup 1.0000x reference)
#include <cuda_runtime.h>
#include <cstdint>

// Sparsemax along dim=-1 for X[4096, 32000] fp32.
//
// Math: sparsemax(x) = max(x - tau, 0) with tau s.t. sum(max(x - tau, 0)) = 1.
// Key bounds: max(x) - 1 <= tau < max(x), so the support is a subset of
// candidates C = { x_i > max(x) - 1 }  (~31 elements for N(0,1), d=32000).
// Fixed-point iteration tau <- (sum_{x>tau} x - 1) / #{x>tau}, starting at
// tau0 = max - 1, is monotone nondecreasing and converges finitely
// (Newton on the convex piecewise-linear f(tau) = sum(x-tau)_+ - 1).
//
// Layout: one CTA per row, 1024 threads, 8 float4 per thread (row lives in
// registers: read input exactly once, write output exactly once).

#define NTHREADS 1024
#define NVEC     8
#define D        32000
#define D4       8000          // float4 per row
#define CAND_MAX 6144          // 24 KB smem candidate buffer (huge safety margin)

__device__ __forceinline__ float warp_max_f(float v) {
    #pragma unroll
    for (int o = 16; o > 0; o >>= 1)
        v = fmaxf(v, __shfl_xor_sync(0xffffffffu, v, o));
    return v;
}

__global__ void __launch_bounds__(NTHREADS, 1)
sparsemax_kernel(const float* __restrict__ X, float* __restrict__ Y)
{
    __shared__ float s_warpf[32];
    __shared__ int   s_warpi[32];
    __shared__ float s_bcast;
    __shared__ int   s_total;
    __shared__ float s_cand[CAND_MAX];

    const int t    = threadIdx.x;
    const int lane = t & 31;
    const int wid  = t >> 5;

    const long long row = blockIdx.x;
    const float4* __restrict__ src = reinterpret_cast<const float4*>(X) + row * (long long)D4;
    float4* __restrict__ dst       = reinterpret_cast<float4*>(Y)       + row * (long long)D4;

    // ---- Pass 1: load row into registers, running max -------------------
    float4 v[NVEC];
    float vmax = -__int_as_float(0x7f800000); // -inf
    #pragma unroll
    for (int i = 0; i < NVEC; i++) {
        int idx = t + i * NTHREADS;
        if (idx < D4) {
            v[i] = src[idx];
            vmax = fmaxf(vmax, fmaxf(fmaxf(v[i].x, v[i].y), fmaxf(v[i].z, v[i].w)));
        } else {
            float ninf = -__int_as_float(0x7f800000);
            v[i] = make_float4(ninf, ninf, ninf, ninf);
        }
    }

    // ---- Block max reduce ------------------------------------------------
    float wm = warp_max_f(vmax);
    if (lane == 0) s_warpf[wid] = wm;
    __syncthreads();
    if (wid == 0) {
        float m = s_warpf[lane];          // 32 warps exactly
        m = warp_max_f(m);
        if (lane == 0) s_bcast = m;
    }
    __syncthreads();
    const float tau0 = s_bcast - 1.0f;

    // ---- Count candidates (x > tau0) per thread ---------------------------
    int cnt = 0;
    #pragma unroll
    for (int i = 0; i < NVEC; i++) {
        cnt += (v[i].x > tau0) + (v[i].y > tau0) + (v[i].z > tau0) + (v[i].w > tau0);
    }

    // ---- Deterministic exclusive block scan of cnt ------------------------
    int inc = cnt;
    #pragma unroll
    for (int o = 1; o < 32; o <<= 1) {
        int y = __shfl_up_sync(0xffffffffu, inc, o);
        if (lane >= o) inc += y;
    }
    if (lane == 31) s_warpi[wid] = inc;   // warp totals
    __syncthreads();
    if (wid == 0) {
        int wv = s_warpi[lane];
        int wx = wv;
        #pragma unroll
        for (int o = 1; o < 32; o <<= 1) {
            int y = __shfl_up_sync(0xffffffffu, wx, o);
            if (lane >= o) wx += y;
        }
        s_warpi[lane] = wx - wv;          // exclusive warp base
        if (lane == 31) s_total = wx;     // grand total
    }
    __syncthreads();
    int offset = s_warpi[wid] + (inc - cnt);
    const int total = s_total;

    float tau;
    if (total <= CAND_MAX) {
        // ---- Compact candidates into smem (order deterministic) ----------
        #pragma unroll
        for (int i = 0; i < NVEC; i++) {
            if (v[i].x > tau0) s_cand[offset++] = v[i].x;
            if (v[i].y > tau0) s_cand[offset++] = v[i].y;
            if (v[i].z > tau0) s_cand[offset++] = v[i].z;
            if (v[i].w > tau0) s_cand[offset++] = v[i].w;
        }
        __syncthreads();

        // ---- Newton/Michelot on candidate list (warp 0 only) -------------
        if (wid == 0) {
            float tt = tau0;
            for (int iter = 0; iter < 64; iter++) {
                float s = 0.0f; int k = 0;
                for (int j = lane; j < total; j += 32) {
                    float c = s_cand[j];
                    if (c > tt) { s += c; k++; }
                }
                #pragma unroll
                for (int o = 16; o > 0; o >>= 1) {
                    s += __shfl_xor_sync(0xffffffffu, s, o);
                    k += __shfl_xor_sync(0xffffffffu, k, o);
                }
                float nt = (s - 1.0f) / (float)k;   // k >= 1 always (argmax active)
                if (nt == tt) break;
                tt = nt;
            }
            if (lane == 0) s_bcast = tt;
        }
        __syncthreads();
        tau = s_bcast;
    } else {
        // ---- Fallback: block-wide Newton over registers (rare/never) -----
        tau = tau0;
        for (int iter = 0; iter < 64; iter++) {
            float s = 0.0f; int k = 0;
            #pragma unroll
            for (int i = 0; i < NVEC; i++) {
                if (v[i].x > tau) { s += v[i].x; k++; }
                if (v[i].y > tau) { s += v[i].y; k++; }
                if (v[i].z > tau) { s += v[i].z; k++; }
                if (v[i].w > tau) { s += v[i].w; k++; }
            }
            #pragma unroll
            for (int o = 16; o > 0; o >>= 1) {
                s += __shfl_xor_sync(0xffffffffu, s, o);
                k += __shfl_xor_sync(0xffffffffu, k, o);
            }
            if (lane == 0) { s_warpf[wid] = s; s_warpi[wid] = k; }
            __syncthreads();
            if (t == 0) {
                float S = 0.0f; int K = 0;
                #pragma unroll
                for (int w = 0; w < 32; w++) { S += s_warpf[w]; K += s_warpi[w]; }
                s_bcast = (S - 1.0f) / (float)K;
            }
            __syncthreads();
            float nt = s_bcast;
            bool done = (nt == tau);
            tau = nt;
            __syncthreads();
            if (done) break;
        }
    }

    // ---- Pass 3: write output ---------------------------------------------
    #pragma unroll
    for (int i = 0; i < NVEC; i++) {
        int idx = t + i * NTHREADS;
        if (idx < D4) {
            float4 o;
            o.x = fmaxf(v[i].x - tau, 0.0f);
            o.y = fmaxf(v[i].y - tau, 0.0f);
            o.z = fmaxf(v[i].z - tau, 0.0f);
            o.w = fmaxf(v[i].w - tau, 0.0f);
            dst[idx] = o;
        }
    }
}

extern "C" void kernel_launch(void* const* d_in, const int* in_sizes, int n_in,
                              void* d_out, int out_size)
{
    const float* X = (const float*)d_in[0];
    float* Y = (float*)d_out;
    int rows = in_sizes[0] / D;   // 4096
    sparsemax_kernel<<<rows, NTHREADS>>>(X, Y);
}

// round 2
// speedup vs baseline: 1.1782x; 1.1782x over previous
#include <cuda_runtime.h>
#include <cstdint>

// Sparsemax along dim=-1 for X[4096, 32000] fp32. Persistent-CTA pipeline:
//  - row i resident in registers (8 x float4 per thread, 1024 threads)
//  - tau via candidate trick: support subset of {x > max-1} (~31 elems),
//    per-warp ballot compaction + warp0 Newton (deterministic).
//  - while solving tau(i)/storing row i, cp.async.bulk prefetches row i+1
//    into a 128KB smem buffer (mbarrier completion), keeping DRAM busy.
//  - fallback block-register Newton for adversarial rows (e.g. constant).

#define NTHREADS 1024
#define NVEC     8
#define D        32000
#define D4       8000
#define SLOTS    64          // candidate slots per warp (32*64*4B = 8KB)

__device__ __forceinline__ unsigned smem_u32(const void* p) {
    return (unsigned)__cvta_generic_to_shared(p);
}

__device__ __forceinline__ float warp_max_f(float v) {
    #pragma unroll
    for (int o = 16; o > 0; o >>= 1)
        v = fmaxf(v, __shfl_xor_sync(0xffffffffu, v, o));
    return v;
}

__device__ __forceinline__ void mbar_wait(unsigned mbar, unsigned ph) {
    asm volatile(
        "{\n\t"
        ".reg .pred P;\n\t"
        "WAIT_%=: \n\t"
        "mbarrier.try_wait.parity.acquire.cta.shared::cta.b64 P, [%0], %1, 0x989680;\n\t"
        "@P bra.uni DONE_%=;\n\t"
        "bra.uni WAIT_%=;\n\t"
        "DONE_%=: \n\t"
        "}\n\t" :: "r"(mbar), "r"(ph) : "memory");
}

__device__ __forceinline__ void bulk_prefetch(unsigned dst_smem, const float* src,
                                              unsigned bytes, unsigned mbar) {
    asm volatile("mbarrier.arrive.expect_tx.shared.b64 _, [%0], %1;"
                 :: "r"(mbar), "r"(bytes) : "memory");
    asm volatile("cp.async.bulk.shared::cluster.global.mbarrier::complete_tx::bytes "
                 "[%0], [%1], %2, [%3];"
                 :: "r"(dst_smem), "l"(src), "r"(bytes), "r"(mbar) : "memory");
}

__global__ void __launch_bounds__(NTHREADS, 1)
sparsemax_kernel(const float* __restrict__ X, float* __restrict__ Y, int nrows)
{
    __shared__ float s_warpf[32];
    __shared__ int   s_warpcnt[32];
    __shared__ float s_bcast;
    __shared__ float s_tau;
    __shared__ int   s_of;
    __shared__ __align__(8) unsigned long long s_mbar;

    extern __shared__ float s_dyn[];
    float* s_buf  = s_dyn;        // 32000 floats = 128000 B prefetch buffer
    float* s_cand = s_dyn + D;    // 32*64 = 2048 floats candidate regions

    const int t    = threadIdx.x;
    const int lane = t & 31;
    const int wid  = t >> 5;
    const int grid = gridDim.x;
    const unsigned mbar = smem_u32(&s_mbar);
    const float NINF = __int_as_float(0xff800000);

    if (t == 0)
        asm volatile("mbarrier.init.shared.b64 [%0], 1;" :: "r"(mbar) : "memory");
    __syncthreads();

    int row = blockIdx.x;
    if (row >= nrows) return;

    // ---- prologue: load row0 straight from global into registers ----------
    float4 v[NVEC];
    {
        const float4* src = reinterpret_cast<const float4*>(X) + (long long)row * D4;
        #pragma unroll
        for (int i = 0; i < NVEC - 1; i++) v[i] = src[t + i * NTHREADS];
        if (t + (NVEC - 1) * NTHREADS < D4) v[NVEC - 1] = src[t + (NVEC - 1) * NTHREADS];
        else v[NVEC - 1] = make_float4(NINF, NINF, NINF, NINF);
    }
    int next = row + grid;
    if (t == 0 && next < nrows)
        bulk_prefetch(smem_u32(s_buf), X + (long long)next * D, D * 4u, mbar);
    unsigned ph = 0;

    for (;;) {
        // ---- block max --------------------------------------------------
        float vmax = NINF;
        #pragma unroll
        for (int i = 0; i < NVEC; i++)
            vmax = fmaxf(vmax, fmaxf(fmaxf(v[i].x, v[i].y), fmaxf(v[i].z, v[i].w)));
        float wm = warp_max_f(vmax);
        if (lane == 0) s_warpf[wid] = wm;
        if (t == 0) s_of = 0;
        __syncthreads();                                   // B1
        if (wid == 0) {
            float m = warp_max_f(s_warpf[lane]);
            if (lane == 0) s_bcast = m;
        }
        __syncthreads();                                   // B2
        const float tau0 = s_bcast - 1.0f;

        // ---- per-warp ballot compaction of candidates (x > tau0) --------
        {
            int cnt = 0;
            const unsigned lml = (1u << lane) - 1u;
            const int base = wid * SLOTS;
            #pragma unroll
            for (int i = 0; i < NVEC; i++) {
                float xs[4] = {v[i].x, v[i].y, v[i].z, v[i].w};
                #pragma unroll
                for (int c = 0; c < 4; c++) {
                    float x = xs[c];
                    bool p = x > tau0;
                    unsigned m = __ballot_sync(0xffffffffu, p);
                    if (p) {
                        int pos = cnt + __popc(m & lml);
                        if (pos < SLOTS) s_cand[base + pos] = x;
                    }
                    cnt += __popc(m);
                }
            }
            if (lane == 0) { s_warpcnt[wid] = cnt; if (cnt > SLOTS) s_of = 1; }
        }
        __syncthreads();                                   // B3

        // ---- warp0 Newton on candidate list ------------------------------
        if (wid == 0) {
            int n = s_warpcnt[lane]; if (n > SLOTS) n = SLOTS;
            const int base = lane * SLOTS;
            float tt = tau0;
            for (int it = 0; it < 64; it++) {
                float s = 0.0f; int k = 0;
                for (int j = 0; j < n; j++) {
                    float c = s_cand[base + j];
                    if (c > tt) { s += c; k++; }
                }
                #pragma unroll
                for (int o = 16; o > 0; o >>= 1) {
                    s += __shfl_xor_sync(0xffffffffu, s, o);
                    k += __shfl_xor_sync(0xffffffffu, k, o);
                }
                float nt = (s - 1.0f) / (float)k;          // k>=1 (argmax active)
                if (nt == tt) break;
                tt = nt;
            }
            if (lane == 0) s_tau = tt;
        }
        __syncthreads();                                   // B4

        if (s_of) {
            // ---- fallback: block-wide Newton over registers (rare) -------
            float tt = tau0;
            for (int it = 0; it < 64; it++) {
                float s = 0.0f; int k = 0;
                #pragma unroll
                for (int i = 0; i < NVEC; i++) {
                    if (v[i].x > tt) { s += v[i].x; k++; }
                    if (v[i].y > tt) { s += v[i].y; k++; }
                    if (v[i].z > tt) { s += v[i].z; k++; }
                    if (v[i].w > tt) { s += v[i].w; k++; }
                }
                #pragma unroll
                for (int o = 16; o > 0; o >>= 1) {
                    s += __shfl_xor_sync(0xffffffffu, s, o);
                    k += __shfl_xor_sync(0xffffffffu, k, o);
                }
                if (lane == 0) { s_warpf[wid] = s; s_warpcnt[wid] = k; }
                __syncthreads();
                if (t == 0) {
                    float S = 0.0f; int K = 0;
                    #pragma unroll
                    for (int w = 0; w < 32; w++) { S += s_warpf[w]; K += s_warpcnt[w]; }
                    s_bcast = (S - 1.0f) / (float)K;
                }
                __syncthreads();
                float nt = s_bcast;
                if (nt == tt) break;                       // uniform
                tt = nt;
            }
            if (t == 0) s_tau = tt;
            __syncthreads();
        }
        const float tau = s_tau;

        // ---- store output for this row -----------------------------------
        {
            float4* dst = reinterpret_cast<float4*>(Y) + (long long)row * D4;
            #pragma unroll
            for (int i = 0; i < NVEC; i++) {
                int idx = t + i * NTHREADS;
                if (i < NVEC - 1 || idx < D4) {
                    float4 o;
                    o.x = fmaxf(v[i].x - tau, 0.0f);
                    o.y = fmaxf(v[i].y - tau, 0.0f);
                    o.z = fmaxf(v[i].z - tau, 0.0f);
                    o.w = fmaxf(v[i].w - tau, 0.0f);
                    dst[idx] = o;
                }
            }
        }

        if (next >= nrows) break;

        // ---- wait prefetch, copy smem -> regs, issue next prefetch -------
        mbar_wait(mbar, ph);
        ph ^= 1u;
        {
            const float4* sb4 = reinterpret_cast<const float4*>(s_buf);
            #pragma unroll
            for (int i = 0; i < NVEC - 1; i++) v[i] = sb4[t + i * NTHREADS];
            if (t + (NVEC - 1) * NTHREADS < D4) v[NVEC - 1] = sb4[t + (NVEC - 1) * NTHREADS];
            // (tail lanes keep -inf padding from prologue)
        }
        __syncthreads();                                   // B5: s_buf free
        int nn = next + grid;
        if (t == 0 && nn < nrows)
            bulk_prefetch(smem_u32(s_buf), X + (long long)nn * D, D * 4u, mbar);
        row = next;
        next = nn;
    }
}

extern "C" void kernel_launch(void* const* d_in, const int* in_sizes, int n_in,
                              void* d_out, int out_size)
{
    const float* X = (const float*)d_in[0];
    float* Y = (float*)d_out;
    int rows = in_sizes[0] / D;                 // 4096

    int sms = 148;
    cudaDeviceGetAttribute(&sms, cudaDevAttrMultiProcessorCount, 0);
    int grid = (rows < sms) ? rows : sms;       // persistent: one CTA per SM

    size_t dyn = (size_t)(D + 32 * SLOTS) * sizeof(float);   // 128000 + 8192
    cudaFuncSetAttribute(sparsemax_kernel,
                         cudaFuncAttributeMaxDynamicSharedMemorySize, (int)dyn);
    sparsemax_kernel<<<grid, NTHREADS, dyn>>>(X, Y, rows);
}